// round 11
// baseline (speedup 1.0000x reference)
#include <cuda_runtime.h>
#include <stdint.h>
#include <math.h>

#define HH 512
#define WW 512
#define HWV (HH*WW)
#define NB 16
#define NB0 8
#define MM 2048
#define SCAP 32768

// ---------------- compile-time taps ----------------
__host__ __device__ constexpr double cexp(double x) {
  double y = x < 0 ? -x : x;
  int n = (int)y;
  double f = y - n;
  double term = 1.0, sum = 1.0;
  for (int i = 1; i < 28; i++) { term = term * f / (double)i; sum += term; }
  double en = 1.0;
  for (int i = 0; i < n; i++) en *= 2.71828182845904523536028747135;
  double r = en * sum;
  return x < 0 ? 1.0 / r : r;
}
__host__ __device__ constexpr float gtap(int i) {
  double s = 0.0, gi = 0.0;
  for (int j = 0; j < 25; j++) {
    double xx = -1.0 + 2.0 * (double)j / 24.0;
    double g = cexp(-xx * xx / 0.5);
    if (j == i) gi = g;
    s += g;
  }
  return (float)(gi / s);
}
__host__ __device__ constexpr float wctap(int i) {
  double xx = -2.0 + 4.0 * (double)i / 50.0;
  return (float)cexp(-xx * xx);
}

// scalar scatter (horizontal conv)
template<int K, int KMAX, int Q, int D, int TMAX, int TSEL>
__device__ __forceinline__ void scat(float x, float* acc) {
  if constexpr (K < KMAX) {
    constexpr int t = Q - D - K;
    if constexpr (t >= 0 && t <= TMAX) {
      constexpr float tp = (TSEL == 0) ? gtap((t >= 0 && t <= TMAX) ? t : 0)
                                       : wctap((t >= 0 && t <= TMAX) ? t : 0);
      acc[K] = fmaf(tp, x, acc[K]);
    }
    scat<K + 1, KMAX, Q, D, TMAX, TSEL>(x, acc);
  }
}
template<int G4, int GMAX, int KMAX, int D, int TMAX, int TSEL>
__device__ __forceinline__ void conv4(const float4* w4, float* acc) {
  if constexpr (G4 < GMAX) {
    float4 X = w4[G4];
    scat<0, KMAX, 4 * G4 + 0, D, TMAX, TSEL>(X.x, acc);
    scat<0, KMAX, 4 * G4 + 1, D, TMAX, TSEL>(X.y, acc);
    scat<0, KMAX, 4 * G4 + 2, D, TMAX, TSEL>(X.z, acc);
    scat<0, KMAX, 4 * G4 + 3, D, TMAX, TSEL>(X.w, acc);
    conv4<G4 + 1, GMAX, KMAX, D, TMAX, TSEL>(w4, acc);
  }
}
// float2 scatter (vertical convs)
template<int K, int KMAX, int Q, int TMAX, int TSEL>
__device__ __forceinline__ void scat2(float2 x, float2* acc) {
  if constexpr (K < KMAX) {
    constexpr int t = Q - K;
    if constexpr (t >= 0 && t <= TMAX) {
      constexpr float tp = (TSEL == 0) ? gtap((t >= 0 && t <= TMAX) ? t : 0)
                                       : wctap((t >= 0 && t <= TMAX) ? t : 0);
      acc[K].x = fmaf(tp, x.x, acc[K].x);
      acc[K].y = fmaf(tp, x.y, acc[K].y);
    }
    scat2<K + 1, KMAX, Q, TMAX, TSEL>(x, acc);
  }
}
template<int R, int RMAX, int KMAX, int TMAX, int TSEL, bool CHK>
__device__ __forceinline__ void vloop2(const float2* p, int hlo, float2* acc) {
  if constexpr (R < RMAX) {
    float2 x = make_float2(0.f, 0.f);
    if (!CHK || ((unsigned)(hlo + R) < (unsigned)HH)) x = p[R * (WW / 2)];
    scat2<0, KMAX, R, TMAX, TSEL>(x, acc);
    vloop2<R + 1, RMAX, KMAX, TMAX, TSEL, CHK>(p, hlo, acc);
  }
}
template<int R, int RMAX, bool CHK>
__device__ __forceinline__ void vmloop2(const float2* ps, const float2* pd, int hlo,
                                        float2* as, float2* ad) {
  if constexpr (R < RMAX) {
    float2 xs = make_float2(0.f, 0.f), xd = make_float2(0.f, 0.f);
    if (!CHK || ((unsigned)(hlo + R) < (unsigned)HH)) {
      xs = ps[R * (WW / 2)];
      xd = pd[R * (WW / 2)];
    }
    scat2<0, 8, R, 24, 0>(xs, as);
    scat2<0, 8, R, 24, 0>(xd, ad);
    vmloop2<R + 1, RMAX, CHK>(ps, pd, hlo, as, ad);
  }
}

// ---------------- device scratch ----------------
__device__ float g_WCP[52];
__device__ float g_t1a[NB*HWV];
__device__ float g_t1b[NB*HWV];
__device__ float g_t1c[NB*HWV];
__device__ float g_ps[NB*128];
__device__ float g_mpart[NB*128*4];
__device__ int   g_svcnt[NB];
__device__ float g_svval[NB*SCAP];
__device__ int   g_svidx[NB*SCAP];
__device__ int   g_kidx[NB*MM];
__device__ float g_ssl[NB*MM];
__device__ unsigned char g_slg[NB*MM];
__device__ float g_lse[NB];
__device__ float g_spart[NB*8];

// ---------------- reductions ----------------
__device__ __forceinline__ float blkMax1024(float v, float* red) {
  int t = threadIdx.x;
  red[t] = v; __syncthreads();
  for (int s = 512; s > 0; s >>= 1) {
    if (t < s) red[t] = fmaxf(red[t], red[t + s]);
    __syncthreads();
  }
  float r = red[0]; __syncthreads();
  return r;
}
__device__ __forceinline__ float blkSum1024(float v, float* red) {
  int t = threadIdx.x;
  red[t] = v; __syncthreads();
  for (int s = 512; s > 0; s >>= 1) {
    if (t < s) red[t] += red[t + s];
    __syncthreads();
  }
  float r = red[0]; __syncthreads();
  return r;
}
__device__ __forceinline__ float blkSum256(float v, float* red, int t) {
  red[t] = v; __syncthreads();
  for (int s = 128; s > 0; s >>= 1) {
    if (t < s) red[t] += red[t + s];
    __syncthreads();
  }
  float r = red[0]; __syncthreads();
  return r;
}
__device__ __forceinline__ float blkSum128(float v, float* red, int t) {
  red[t] = v; __syncthreads();
  for (int s = 64; s > 0; s >>= 1) {
    if (t < s) red[t] += red[t + s];
    __syncthreads();
  }
  float r = red[0]; __syncthreads();
  return r;
}

// ---------------- fused horizontal pass (+ init duties) ----------------
__global__ __launch_bounds__(256) void k_hall(const float* __restrict__ score,
                                              const float* __restrict__ hd) {
  __shared__ float sE[4][568];
  __shared__ float sD[4][536];
  __shared__ float red[256];
  int b = blockIdx.y;
  int tx = threadIdx.x, ty = threadIdx.y;    // (64,4)
  int h = blockIdx.x * 4 + ty;
  int tid = ty * 64 + tx;
  if (blockIdx.x == 0 && tid == 0) {
    g_svcnt[b] = 0;
    if (b == 0) {
      float p = 0.f;
      for (int i = 0; i < 51; i++) {
        float x = -2.0f + (4.0f / 50.0f) * (float)i;
        g_WCP[i] = p;
        p += expf(-x * x);
      }
      g_WCP[51] = p;
    }
  }
  const float* srow = score + (size_t)b * HWV + (size_t)h * WW;
  const float* drow = hd + (size_t)b * HWV + (size_t)h * WW;
  float esum = 0.f;
  for (int c = tx; c < 568; c += 64) {
    int w = c - 28;
    float e = 0.f;
    if (w >= 0 && w < WW) e = __expf(srow[w]);
    sE[ty][c] = e;
    esum += e;
  }
  for (int c = tx; c < 536; c += 64) {
    int w = c - 12;
    sD[ty][c] = (w >= 0 && w < WW) ? drow[w] : 0.f;
  }
  __syncthreads();
  int wbase = 8 * tx;
  size_t obase = (size_t)b * HWV + (size_t)h * WW + wbase;
  {
    float acc[8];
#pragma unroll
    for (int k = 0; k < 8; k++) acc[k] = 0.f;
    conv4<0, 16, 8, 3, 50, 1>((const float4*)&sE[ty][wbase], acc);
    float4* o = (float4*)(g_t1c + obase);
    o[0] = make_float4(acc[0], acc[1], acc[2], acc[3]);
    o[1] = make_float4(acc[4], acc[5], acc[6], acc[7]);
  }
  {
    float acc[8];
#pragma unroll
    for (int k = 0; k < 8; k++) acc[k] = 0.f;
    conv4<4, 12, 8, 16, 24, 0>((const float4*)&sE[ty][wbase], acc);
#pragma unroll
    for (int k = 0; k < 8; k++) {
      int w = wbase + k;
      if (w < 12 || w >= WW - 12) acc[k] = 0.f;
    }
    float4* o = (float4*)(g_t1a + obase);
    o[0] = make_float4(acc[0], acc[1], acc[2], acc[3]);
    o[1] = make_float4(acc[4], acc[5], acc[6], acc[7]);
  }
  {
    float acc[8];
#pragma unroll
    for (int k = 0; k < 8; k++) acc[k] = 0.f;
    conv4<0, 8, 8, 0, 24, 0>((const float4*)&sD[ty][wbase], acc);
    float4* o = (float4*)(g_t1b + obase);
    o[0] = make_float4(acc[0], acc[1], acc[2], acc[3]);
    o[1] = make_float4(acc[4], acc[5], acc[6], acc[7]);
  }
  esum = blkSum256(esum, red, tid);
  if (tid == 0) g_ps[b * 128 + blockIdx.x] = esum;
}

// ---------------- vmatch tile body ----------------
__device__ void vmatch_body(int b, int bx, int by) {
  __shared__ float red[256];
  int tx = threadIdx.x, ty = threadIdx.y;
  int c2 = bx * 32 + tx;
  int hb = by * 64 + ty * 8;
  int tid = ty * 32 + tx;
  float pv = (tid < 128) ? g_ps[b * 128 + tid] : 0.f;
  float Z = blkSum256(pv, red, tid);
  float invz = 1.0f / Z;
  const float2* ps = (const float2*)(g_t1a + (size_t)b * HWV);
  const float2* pd = (const float2*)(g_t1b + (size_t)b * HWV);
  float2 as[8], ad[8];
#pragma unroll
  for (int k = 0; k < 8; k++) {
    as[k] = make_float2(0.f, 0.f);
    ad[k] = make_float2(0.f, 0.f);
  }
  int hlo = hb - 12;
  const float2* pps = ps + (size_t)hlo * (WW / 2) + c2;
  const float2* ppd = pd + (size_t)hlo * (WW / 2) + c2;
  if (hlo >= 0 && hlo + 31 < HH) vmloop2<0, 32, false>(pps, ppd, hlo, as, ad);
  else                           vmloop2<0, 32, true>(pps, ppd, hlo, as, ad);
  float zsum = 0.f, sdsum = 0.f, sdv = 0.f, sdlsd = 0.f;
#pragma unroll
  for (int k = 0; k < 8; k++) {
#pragma unroll
    for (int c = 0; c < 2; c++) {
      float a = c ? as[k].y : as[k].x;
      float sd = c ? ad[k].y : ad[k].x;
      float s = fmaf(invz, a, 1e-8f);
      zsum += s;
      sdsum += sd;
      if (sd > 0.f) {
        sdv = fmaf(sd, __logf(s), sdv);
        sdlsd = fmaf(sd, __logf(sd), sdlsd);
      }
    }
  }
  zsum = blkSum256(zsum, red, tid);
  sdsum = blkSum256(sdsum, red, tid);
  sdv = blkSum256(sdv, red, tid);
  sdlsd = blkSum256(sdlsd, red, tid);
  if (tid == 0) {
    int bi = by * 8 + bx;
    float* p = g_mpart + ((size_t)b * 128 + bi) * 4;
    p[0] = zsum; p[1] = sdsum; p[2] = sdv; p[3] = sdlsd;
  }
}

// ---------------- vcnms tile body (vertical coverage conv + reweight + 5x5 NMS) ----------------
__device__ void vcnms_body(const float* __restrict__ score, int b, int bx, int by) {
  __shared__ float red[256];
  __shared__ float2 xch[8][4][33];
  __shared__ int scnt, sbase;
  int r0 = by * 128;
  int tx = threadIdx.x, ty = threadIdx.y;
  int tid = ty * 32 + tx;
  if (tid == 0) scnt = 0;
  float pv = (tid < 128) ? g_ps[b * 128 + tid] : 0.f;
  float Z = blkSum256(pv, red, tid);
  float invz = 1.0f / Z;
  int c2 = 30 * bx - 1 + tx;
  int c2c = min(max(c2, 0), 255);
  bool colok = (c2 >= 0 && c2 < 256);
  int rowbase = r0 - 2 + ty * 17;
  int hlo = rowbase - 25;
  const float2* pin = (const float2*)(g_t1c + (size_t)b * HWV);
  float2 s[17];
#pragma unroll
  for (int k = 0; k < 17; k++) s[k] = make_float2(0.f, 0.f);
  const float2* p = pin + (ptrdiff_t)hlo * 256 + c2c;
  if (hlo >= 0 && hlo + 66 < HH) vloop2<0, 67, 17, 50, 1, false>(p, hlo, s);
  else                           vloop2<0, 67, 17, 50, 1, true>(p, hlo, s);
  int w0 = 2 * c2, w1 = w0 + 1;
  int wc0 = min(max(w0, 0), 511), wc1 = min(max(w1, 0), 511);
  int jlo0 = max(25 - wc0, 0), jhi0 = min(536 - wc0, 50);
  int jlo1 = max(25 - wc1, 0), jhi1 = min(536 - wc1, 50);
  float Tw0 = g_WCP[jhi0 + 1] - g_WCP[jlo0];
  float Tw1 = g_WCP[jhi1 + 1] - g_WCP[jlo1];
  const float2* sc = (const float2*)(score + (size_t)b * HWV);
#pragma unroll
  for (int k = 0; k < 17; k++) {
    int g = rowbase + k;
    bool rowok = (g >= 0 && g < HH);
    float2 e = make_float2(0.f, 0.f);
    if (rowok) e = sc[(size_t)(rowok ? g : 0) * 256 + c2c];
    int gc = min(max(g, 0), 511);
    int ilo = max(25 - gc, 0), ihi = min(536 - gc, 50);
    float Tv = g_WCP[ihi + 1] - g_WCP[ilo];
    float ld0 = 1e4f * (invz * s[k].x + 1e-6f * Tw0 * Tv);
    float ld1 = 1e4f * (invz * s[k].y + 1e-6f * Tw1 * Tv);
    float v0 = __expf(e.x) * invz * rsqrtf(ld0 + 1e-8f);
    float v1 = __expf(e.y) * invz * rsqrtf(ld1 + 1e-8f);
    bool ok = rowok && colok;
    s[k].x = ok ? v0 : -INFINITY;
    s[k].y = ok ? v1 : -INFINITY;
  }
  xch[ty][0][tx] = s[0];  xch[ty][1][tx] = s[1];
  xch[ty][2][tx] = s[15]; xch[ty][3][tx] = s[16];
  __syncthreads();
  float2 ninf = make_float2(-INFINITY, -INFINITY);
  float2 bm2 = (ty > 0) ? xch[ty - 1][2][tx] : ninf;
  float2 bm1 = (ty > 0) ? xch[ty - 1][3][tx] : ninf;
  float2 ap0 = (ty < 7) ? xch[ty + 1][0][tx] : ninf;
  float2 ap1 = (ty < 7) ? xch[ty + 1][1][tx] : ninf;
  float mv[6]; int mi[6]; int mine = 0;
#pragma unroll
  for (int k = 0; k < 17; k++) {
    float2 a  = (k >= 2) ? s[k - 2] : (k == 1 ? bm1 : bm2);
    float2 bb = (k >= 1) ? s[k - 1] : bm1;
    float2 c  = s[k];
    float2 d  = (k < 16) ? s[k + 1] : ap0;
    float2 ee = (k < 15) ? s[k + 2] : (k == 15 ? ap0 : ap1);
    float2 vm;
    vm.x = fmaxf(fmaxf(fmaxf(a.x, bb.x), fmaxf(c.x, d.x)), ee.x);
    vm.y = fmaxf(fmaxf(fmaxf(a.y, bb.y), fmaxf(c.y, d.y)), ee.y);
    float Lx = __shfl_up_sync(0xffffffffu, vm.x, 1);
    float Ly = __shfl_up_sync(0xffffffffu, vm.y, 1);
    float Rx = __shfl_down_sync(0xffffffffu, vm.x, 1);
    float Ry = __shfl_down_sync(0xffffffffu, vm.y, 1);
    float Mx = fmaxf(fmaxf(Lx, Ly), fmaxf(fmaxf(vm.x, vm.y), Rx));
    float My = fmaxf(fmaxf(Ly, vm.x), fmaxf(fmaxf(vm.y, Rx), Ry));
    int g = rowbase + k;
    bool rowT = (g >= r0) && (g < r0 + 128) && (g < HH);
    if (rowT && tx >= 1 && tx <= 30) {
      if (w0 < WW && c.x == Mx) {
        if (mine < 6) { mv[mine] = c.x; mi[mine] = g * WW + w0; }
        mine++;
      }
      if (w1 < WW && c.y == My) {
        if (mine < 6) { mv[mine] = c.y; mi[mine] = g * WW + w1; }
        mine++;
      }
    }
  }
  int cnt = min(mine, 6);
  int loc = 0;
  if (cnt) loc = atomicAdd(&scnt, cnt);
  __syncthreads();
  if (tid == 0) sbase = atomicAdd(&g_svcnt[b], scnt);
  __syncthreads();
  int base = sbase + loc;
  for (int i = 0; i < cnt; i++) {
    int pp = base + i;
    if (pp < SCAP) {
      g_svval[(size_t)b * SCAP + pp] = mv[i];
      g_svidx[(size_t)b * SCAP + pp] = mi[i];
    }
  }
}

// ---------------- merged launch: vmatch (64 tiles/img) + vcnms (36 tiles/img) ----------------
__global__ __launch_bounds__(256) void k_vboth(const float* __restrict__ score) {
  int f = blockIdx.x;
  int b = blockIdx.y;
  if (f < 64) vmatch_body(b, f & 7, f >> 3);
  else { int g = f - 64; vcnms_body(score, b, g % 9, g / 9); }
}

// ---------------- top-2048 radix select + gather + masked LSE ----------------
__global__ __launch_bounds__(1024) void k_topk(const float* __restrict__ scoremap,
                                               const float* __restrict__ vA,
                                               const float* __restrict__ vB) {
  int x = blockIdx.x;
  int n = g_svcnt[x]; if (n > SCAP) n = SCAP;
  const float* vals = g_svval + (size_t)x * SCAP;
  const int* idxs = g_svidx + (size_t)x * SCAP;
  int* out = g_kidx + (size_t)x * MM;
  __shared__ int hist[256];
  __shared__ int suf[256];
  __shared__ float red[1024];
  __shared__ int sh_k, sh_dig, sh_ngt, sh_neq;
  int t = threadIdx.x;
  unsigned int prefix = 0;
  int k = MM;
  for (int lvl = 0; lvl < 4; lvl++) {
    int shift = 24 - 8 * lvl;
    if (t < 256) hist[t] = 0;
    __syncthreads();
    for (int i = t; i < n; i += 1024) {
      unsigned int u = __float_as_uint(vals[i]);
      bool ok = (lvl == 0) || ((u >> (shift + 8)) == (prefix >> (shift + 8)));
      if (ok) atomicAdd(&hist[(u >> shift) & 255], 1);
    }
    __syncthreads();
    if (t < 256) suf[t] = hist[t];
    __syncthreads();
    for (int off = 1; off < 256; off <<= 1) {
      int v = 0;
      if (t < 256) v = suf[t] + ((t + off < 256) ? suf[t + off] : 0);
      __syncthreads();
      if (t < 256) suf[t] = v;
      __syncthreads();
    }
    if (t < 256) {
      int nxt = (t == 255) ? 0 : suf[t + 1];
      if (suf[t] >= k && nxt < k) { sh_dig = t; sh_k = k - nxt; }
    }
    if (t == 0 && suf[0] < k) { sh_dig = 0; sh_k = k; }
    __syncthreads();
    k = sh_k;
    prefix |= ((unsigned int)sh_dig) << shift;
    __syncthreads();
  }
  unsigned int T = prefix;
  if (t == 0) { sh_ngt = 0; sh_neq = 0; }
  __syncthreads();
  for (int i = t; i < n; i += 1024) {
    unsigned int u = __float_as_uint(vals[i]);
    if (u > T) { int p = atomicAdd(&sh_ngt, 1); if (p < MM) out[p] = idxs[i]; }
  }
  __syncthreads();
  int base = sh_ngt;
  for (int i = t; i < n; i += 1024) {
    unsigned int u = __float_as_uint(vals[i]);
    if (u == T) { int p = atomicAdd(&sh_neq, 1); if (base + p < MM) out[base + p] = idxs[i]; }
  }
  __syncthreads();
  int dir = (x >= NB0) ? 1 : 0;
  int b = dir ? x - NB0 : x;
  const float* valid = (dir ? vB : vA) + (size_t)b * HWV;
  const float* logit = scoremap + (size_t)x * HWV;
  float mv = -INFINITY;
  for (int i = t; i < MM; i += 1024) {
    int id = out[i];
    float sl = logit[id];
    unsigned char lg = (valid[id] > 0.f) ? 1 : 0;
    g_ssl[(size_t)x * MM + i] = sl;
    g_slg[(size_t)x * MM + i] = lg;
    mv = fmaxf(mv, lg ? sl : -1e9f);
  }
  mv = blkMax1024(mv, red);
  float z = 0.f;
  for (int i = t; i < MM; i += 1024) {
    float ml = g_slg[(size_t)x * MM + i] ? g_ssl[(size_t)x * MM + i] : -1e9f;
    z += expf(ml - mv);
  }
  z = blkSum1024(z, red);
  if (t == 0) g_lse[x] = mv + logf(z);
}

// ---------------- distance + reward + weighted loss partials (2 queries/thread) ----------------
__global__ __launch_bounds__(128) void k_dist(const float* __restrict__ wA,
                                              const float* __restrict__ wB) {
  __shared__ float4 sp[MM];
  __shared__ float red[128];
  int x = blockIdx.x, seg = blockIdx.y;
  int dir = (x >= NB0) ? 1 : 0;
  int b = dir ? x - NB0 : x;
  int oppx = dir ? b : (NB0 + b);
  const int* opp = g_kidx + (size_t)oppx * MM;
  const int* own = g_kidx + (size_t)x * MM;
  const float4* warp = (const float4*)((dir ? wB : wA) + (size_t)b * HWV * 4);
  int t = threadIdx.x;
  for (int i = t; i < MM; i += 128) {
    int id = opp[i]; int hh = id >> 9, ww = id & 511;
    float px = ((float)ww + 0.5f) * (2.0f / (float)WW) - 1.0f;
    float py = ((float)hh + 0.5f) * (2.0f / (float)HH) - 1.0f;
    sp[i] = make_float4(2.0f * px, 2.0f * py, fmaf(px, px, py * py), 0.f);
  }
  __syncthreads();
  int i0 = seg * 128 + t;
  int i1 = i0 + 1024;
  float4 q0 = warp[own[i0]];
  float4 q1 = warp[own[i1]];
  float tx0 = q0.z, ty0 = q0.w;
  float tx1 = q1.z, ty1 = q1.w;
  float a0 = -3.4e38f, a1 = -3.4e38f, a2 = -3.4e38f, a3 = -3.4e38f;
  float b0 = -3.4e38f, b1 = -3.4e38f, b2 = -3.4e38f, b3 = -3.4e38f;
#pragma unroll 2
  for (int j = 0; j < MM; j += 4) {
    float4 p0 = sp[j], p1 = sp[j + 1], p2 = sp[j + 2], p3 = sp[j + 3];
    a0 = fmaxf(a0, fmaf(p0.x, tx0, fmaf(p0.y, ty0, -p0.z)));
    a1 = fmaxf(a1, fmaf(p1.x, tx0, fmaf(p1.y, ty0, -p1.z)));
    a2 = fmaxf(a2, fmaf(p2.x, tx0, fmaf(p2.y, ty0, -p2.z)));
    a3 = fmaxf(a3, fmaf(p3.x, tx0, fmaf(p3.y, ty0, -p3.z)));
    b0 = fmaxf(b0, fmaf(p0.x, tx1, fmaf(p0.y, ty1, -p0.z)));
    b1 = fmaxf(b1, fmaf(p1.x, tx1, fmaf(p1.y, ty1, -p1.z)));
    b2 = fmaxf(b2, fmaf(p2.x, tx1, fmaf(p2.y, ty1, -p2.z)));
    b3 = fmaxf(b3, fmaf(p3.x, tx1, fmaf(p3.y, ty1, -p3.z)));
  }
  float m0 = fmaxf(fmaxf(a0, a1), fmaxf(a2, a3));
  float m1 = fmaxf(fmaxf(b0, b1), fmaxf(b2, b3));
  float dm0 = fmaxf(fmaf(tx0, tx0, ty0 * ty0) - m0, 0.f);
  float dm1 = fmaxf(fmaf(tx1, tx1, ty1 * ty1) - m1, 0.f);
  float r0 = expf(-100.0f * sqrtf(dm0 + 1e-12f));
  float r1 = expf(-100.0f * sqrtf(dm1 + 1e-12f));
  float lse = g_lse[x];
  float c0 = g_slg[(size_t)x * MM + i0] ? r0 * (g_ssl[(size_t)x * MM + i0] - lse) : 0.f;
  float c1 = g_slg[(size_t)x * MM + i1] ? r1 * (g_ssl[(size_t)x * MM + i1] - lse) : 0.f;
  float contrib = blkSum128(c0 + c1, red, t);
  if (t == 0) g_spart[x * 8 + seg] = contrib;
}

// ---------------- final combine ----------------
__global__ __launch_bounds__(256) void k_final(float* __restrict__ out) {
  __shared__ float sZ[128], sS[128], sV[128], sD[128];
  __shared__ float sm[16];
  __shared__ float ssp[128];
  int t = threadIdx.x;
  if (t < 128) {
    int img = t >> 3, seg = t & 7;
    float z = 0.f, s = 0.f, v = 0.f, d = 0.f;
    for (int j = 0; j < 16; j++) {
      const float* p = g_mpart + ((size_t)img * 128 + seg * 16 + j) * 4;
      z += p[0]; s += p[1]; v += p[2]; d += p[3];
    }
    sZ[t] = z; sS[t] = s; sV[t] = v; sD[t] = d;
    ssp[t] = g_spart[t];
  }
  __syncthreads();
  if (t < 16) {
    float z = 0.f, s = 0.f, v = 0.f, d = 0.f;
    for (int seg = 0; seg < 8; seg++) {
      z += sZ[t * 8 + seg]; s += sS[t * 8 + seg];
      v += sV[t * 8 + seg]; d += sD[t * 8 + seg];
    }
    float inv = 1.0f / s;
    sm[t] = inv * (d - v) - logf(s) + logf(z);
  }
  __syncthreads();
  if (t == 0) {
    float sp = 0.f;
    for (int i = 0; i < 128; i++) sp += ssp[i];
    float m = 0.f;
    for (int i = 0; i < 16; i++) m += sm[i];
    out[0] = -sp + m * (1.0f / 16.0f);
  }
}

// ---------------- host launcher ----------------
extern "C" void kernel_launch(void* const* d_in, const int* in_sizes, int n_in,
                              void* d_out, int out_size) {
  (void)in_sizes; (void)n_in; (void)out_size;
  const float* scoremap = (const float*)d_in[0];
  const float* wA = (const float*)d_in[1];
  const float* wB = (const float*)d_in[2];
  const float* vA = (const float*)d_in[3];
  const float* vB = (const float*)d_in[4];
  const float* hd = (const float*)d_in[5];
  float* out = (float*)d_out;

  dim3 hg(HH / 4, NB);
  dim3 hb(64, 4);
  dim3 bg(100, NB);
  dim3 vb(32, 8);
  dim3 dg(NB, 8);

  k_hall<<<hg, hb>>>(scoremap, hd);
  k_vboth<<<bg, vb>>>(scoremap);
  k_topk<<<NB, 1024>>>(scoremap, vA, vB);
  k_dist<<<dg, 128>>>(wA, wB);
  k_final<<<1, 256>>>(out);
}

// round 12
// speedup vs baseline: 1.8299x; 1.8299x over previous
#include <cuda_runtime.h>
#include <stdint.h>
#include <math.h>

#define HH 512
#define WW 512
#define HWV (HH*WW)
#define NB 16
#define NB0 8
#define MM 2048
#define SCAP 32768

// ---------------- compile-time taps ----------------
__host__ __device__ constexpr double cexp(double x) {
  double y = x < 0 ? -x : x;
  int n = (int)y;
  double f = y - n;
  double term = 1.0, sum = 1.0;
  for (int i = 1; i < 28; i++) { term = term * f / (double)i; sum += term; }
  double en = 1.0;
  for (int i = 0; i < n; i++) en *= 2.71828182845904523536028747135;
  double r = en * sum;
  return x < 0 ? 1.0 / r : r;
}
__host__ __device__ constexpr float gtap(int i) {
  double s = 0.0, gi = 0.0;
  for (int j = 0; j < 25; j++) {
    double xx = -1.0 + 2.0 * (double)j / 24.0;
    double g = cexp(-xx * xx / 0.5);
    if (j == i) gi = g;
    s += g;
  }
  return (float)(gi / s);
}
__host__ __device__ constexpr float wctap(int i) {
  double xx = -2.0 + 4.0 * (double)i / 50.0;
  return (float)cexp(-xx * xx);
}

// scalar scatter (horizontal conv)
template<int K, int KMAX, int Q, int D, int TMAX, int TSEL>
__device__ __forceinline__ void scat(float x, float* acc) {
  if constexpr (K < KMAX) {
    constexpr int t = Q - D - K;
    if constexpr (t >= 0 && t <= TMAX) {
      constexpr float tp = (TSEL == 0) ? gtap((t >= 0 && t <= TMAX) ? t : 0)
                                       : wctap((t >= 0 && t <= TMAX) ? t : 0);
      acc[K] = fmaf(tp, x, acc[K]);
    }
    scat<K + 1, KMAX, Q, D, TMAX, TSEL>(x, acc);
  }
}
template<int G4, int GMAX, int KMAX, int D, int TMAX, int TSEL>
__device__ __forceinline__ void conv4(const float4* w4, float* acc) {
  if constexpr (G4 < GMAX) {
    float4 X = w4[G4];
    scat<0, KMAX, 4 * G4 + 0, D, TMAX, TSEL>(X.x, acc);
    scat<0, KMAX, 4 * G4 + 1, D, TMAX, TSEL>(X.y, acc);
    scat<0, KMAX, 4 * G4 + 2, D, TMAX, TSEL>(X.z, acc);
    scat<0, KMAX, 4 * G4 + 3, D, TMAX, TSEL>(X.w, acc);
    conv4<G4 + 1, GMAX, KMAX, D, TMAX, TSEL>(w4, acc);
  }
}
// float2 scatter (vertical convs)
template<int K, int KMAX, int Q, int TMAX, int TSEL>
__device__ __forceinline__ void scat2(float2 x, float2* acc) {
  if constexpr (K < KMAX) {
    constexpr int t = Q - K;
    if constexpr (t >= 0 && t <= TMAX) {
      constexpr float tp = (TSEL == 0) ? gtap((t >= 0 && t <= TMAX) ? t : 0)
                                       : wctap((t >= 0 && t <= TMAX) ? t : 0);
      acc[K].x = fmaf(tp, x.x, acc[K].x);
      acc[K].y = fmaf(tp, x.y, acc[K].y);
    }
    scat2<K + 1, KMAX, Q, TMAX, TSEL>(x, acc);
  }
}
template<int R, int RMAX, int KMAX, int TMAX, int TSEL, bool CHK>
__device__ __forceinline__ void vloop2(const float2* p, int hlo, float2* acc) {
  if constexpr (R < RMAX) {
    float2 x = make_float2(0.f, 0.f);
    if (!CHK || ((unsigned)(hlo + R) < (unsigned)HH)) x = p[R * (WW / 2)];
    scat2<0, KMAX, R, TMAX, TSEL>(x, acc);
    vloop2<R + 1, RMAX, KMAX, TMAX, TSEL, CHK>(p, hlo, acc);
  }
}
template<int R, int RMAX, bool CHK>
__device__ __forceinline__ void vmloop2(const float2* ps, const float2* pd, int hlo,
                                        float2* as, float2* ad) {
  if constexpr (R < RMAX) {
    float2 xs = make_float2(0.f, 0.f), xd = make_float2(0.f, 0.f);
    if (!CHK || ((unsigned)(hlo + R) < (unsigned)HH)) {
      xs = ps[R * (WW / 2)];
      xd = pd[R * (WW / 2)];
    }
    scat2<0, 8, R, 24, 0>(xs, as);
    scat2<0, 8, R, 24, 0>(xd, ad);
    vmloop2<R + 1, RMAX, CHK>(ps, pd, hlo, as, ad);
  }
}

// ---------------- device scratch ----------------
__device__ float g_WCP[52];
__device__ float g_t1a[NB*HWV];
__device__ float g_t1b[NB*HWV];
__device__ float g_t1c[NB*HWV];
__device__ float g_ps[NB*128];
__device__ float g_mpart[NB*128*4];
__device__ int   g_svcnt[NB];
__device__ float g_svval[NB*SCAP];
__device__ int   g_svidx[NB*SCAP];
__device__ int   g_kidx[NB*MM];
__device__ float g_ssl[NB*MM];
__device__ unsigned char g_slg[NB*MM];
__device__ float g_lse[NB];
__device__ float g_spart[NB*8];

// ---------------- reductions ----------------
__device__ __forceinline__ float blkMax1024(float v, float* red) {
  int t = threadIdx.x;
  red[t] = v; __syncthreads();
  for (int s = 512; s > 0; s >>= 1) {
    if (t < s) red[t] = fmaxf(red[t], red[t + s]);
    __syncthreads();
  }
  float r = red[0]; __syncthreads();
  return r;
}
__device__ __forceinline__ float blkSum1024(float v, float* red) {
  int t = threadIdx.x;
  red[t] = v; __syncthreads();
  for (int s = 512; s > 0; s >>= 1) {
    if (t < s) red[t] += red[t + s];
    __syncthreads();
  }
  float r = red[0]; __syncthreads();
  return r;
}
__device__ __forceinline__ float blkSum256(float v, float* red, int t) {
  red[t] = v; __syncthreads();
  for (int s = 128; s > 0; s >>= 1) {
    if (t < s) red[t] += red[t + s];
    __syncthreads();
  }
  float r = red[0]; __syncthreads();
  return r;
}

// ---------------- fused horizontal pass (+ init duties) ----------------
__global__ __launch_bounds__(256) void k_hall(const float* __restrict__ score,
                                              const float* __restrict__ hd) {
  __shared__ float sE[4][568];
  __shared__ float sD[4][536];
  __shared__ float red[256];
  int b = blockIdx.y;
  int tx = threadIdx.x, ty = threadIdx.y;    // (64,4)
  int h = blockIdx.x * 4 + ty;
  int tid = ty * 64 + tx;
  if (blockIdx.x == 0 && tid == 0) {
    g_svcnt[b] = 0;
    if (b == 0) {
      float p = 0.f;
      for (int i = 0; i < 51; i++) {
        float x = -2.0f + (4.0f / 50.0f) * (float)i;
        g_WCP[i] = p;
        p += expf(-x * x);
      }
      g_WCP[51] = p;
    }
  }
  const float* srow = score + (size_t)b * HWV + (size_t)h * WW;
  const float* drow = hd + (size_t)b * HWV + (size_t)h * WW;
  float esum = 0.f;
  for (int c = tx; c < 568; c += 64) {
    int w = c - 28;
    float e = 0.f;
    if (w >= 0 && w < WW) e = __expf(srow[w]);
    sE[ty][c] = e;
    esum += e;
  }
  for (int c = tx; c < 536; c += 64) {
    int w = c - 12;
    sD[ty][c] = (w >= 0 && w < WW) ? drow[w] : 0.f;
  }
  __syncthreads();
  int wbase = 8 * tx;
  size_t obase = (size_t)b * HWV + (size_t)h * WW + wbase;
  {
    float acc[8];
#pragma unroll
    for (int k = 0; k < 8; k++) acc[k] = 0.f;
    conv4<0, 16, 8, 3, 50, 1>((const float4*)&sE[ty][wbase], acc);
    float4* o = (float4*)(g_t1c + obase);
    o[0] = make_float4(acc[0], acc[1], acc[2], acc[3]);
    o[1] = make_float4(acc[4], acc[5], acc[6], acc[7]);
  }
  {
    float acc[8];
#pragma unroll
    for (int k = 0; k < 8; k++) acc[k] = 0.f;
    conv4<4, 12, 8, 16, 24, 0>((const float4*)&sE[ty][wbase], acc);
#pragma unroll
    for (int k = 0; k < 8; k++) {
      int w = wbase + k;
      if (w < 12 || w >= WW - 12) acc[k] = 0.f;
    }
    float4* o = (float4*)(g_t1a + obase);
    o[0] = make_float4(acc[0], acc[1], acc[2], acc[3]);
    o[1] = make_float4(acc[4], acc[5], acc[6], acc[7]);
  }
  {
    float acc[8];
#pragma unroll
    for (int k = 0; k < 8; k++) acc[k] = 0.f;
    conv4<0, 8, 8, 0, 24, 0>((const float4*)&sD[ty][wbase], acc);
    float4* o = (float4*)(g_t1b + obase);
    o[0] = make_float4(acc[0], acc[1], acc[2], acc[3]);
    o[1] = make_float4(acc[4], acc[5], acc[6], acc[7]);
  }
  esum = blkSum256(esum, red, tid);
  if (tid == 0) g_ps[b * 128 + blockIdx.x] = esum;
}

// ---------------- fused vertical convs (s + sd) + matchability partials ----------------
__global__ __launch_bounds__(256) void k_vmatch() {
  __shared__ float red[256];
  int b = blockIdx.z;
  int tx = threadIdx.x, ty = threadIdx.y;
  int c2 = blockIdx.x * 32 + tx;
  int hb = blockIdx.y * 64 + ty * 8;
  int tid = ty * 32 + tx;
  float pv = (tid < 128) ? g_ps[b * 128 + tid] : 0.f;
  float Z = blkSum256(pv, red, tid);
  float invz = 1.0f / Z;
  const float2* ps = (const float2*)(g_t1a + (size_t)b * HWV);
  const float2* pd = (const float2*)(g_t1b + (size_t)b * HWV);
  float2 as[8], ad[8];
#pragma unroll
  for (int k = 0; k < 8; k++) {
    as[k] = make_float2(0.f, 0.f);
    ad[k] = make_float2(0.f, 0.f);
  }
  int hlo = hb - 12;
  const float2* pps = ps + (size_t)hlo * (WW / 2) + c2;
  const float2* ppd = pd + (size_t)hlo * (WW / 2) + c2;
  if (hlo >= 0 && hlo + 31 < HH) vmloop2<0, 32, false>(pps, ppd, hlo, as, ad);
  else                           vmloop2<0, 32, true>(pps, ppd, hlo, as, ad);
  float zsum = 0.f, sdsum = 0.f, sdv = 0.f, sdlsd = 0.f;
#pragma unroll
  for (int k = 0; k < 8; k++) {
#pragma unroll
    for (int c = 0; c < 2; c++) {
      float a = c ? as[k].y : as[k].x;
      float sd = c ? ad[k].y : ad[k].x;
      float s = fmaf(invz, a, 1e-8f);
      zsum += s;
      sdsum += sd;
      if (sd > 0.f) {
        sdv = fmaf(sd, __logf(s), sdv);
        sdlsd = fmaf(sd, __logf(sd), sdlsd);
      }
    }
  }
  zsum = blkSum256(zsum, red, tid);
  sdsum = blkSum256(sdsum, red, tid);
  sdv = blkSum256(sdv, red, tid);
  sdlsd = blkSum256(sdlsd, red, tid);
  if (tid == 0) {
    int bi = blockIdx.y * 8 + blockIdx.x;
    float* p = g_mpart + ((size_t)b * 128 + bi) * 4;
    p[0] = zsum; p[1] = sdsum; p[2] = sdv; p[3] = sdlsd;
  }
}

// ---------------- fused: vertical coverage conv + reweight + 5x5 NMS ----------------
__global__ __launch_bounds__(256) void k_vcnms(const float* __restrict__ score) {
  __shared__ float red[256];
  __shared__ float2 xch[8][4][33];
  __shared__ int scnt, sbase;
  int b = blockIdx.z;
  int bx = blockIdx.x;
  int r0 = blockIdx.y * 128;
  int tx = threadIdx.x, ty = threadIdx.y;
  int tid = ty * 32 + tx;
  if (tid == 0) scnt = 0;
  float pv = (tid < 128) ? g_ps[b * 128 + tid] : 0.f;
  float Z = blkSum256(pv, red, tid);
  float invz = 1.0f / Z;
  int c2 = 30 * bx - 1 + tx;
  int c2c = min(max(c2, 0), 255);
  bool colok = (c2 >= 0 && c2 < 256);
  int rowbase = r0 - 2 + ty * 17;
  int hlo = rowbase - 25;
  const float2* pin = (const float2*)(g_t1c + (size_t)b * HWV);
  float2 s[17];
#pragma unroll
  for (int k = 0; k < 17; k++) s[k] = make_float2(0.f, 0.f);
  const float2* p = pin + (ptrdiff_t)hlo * 256 + c2c;
  if (hlo >= 0 && hlo + 66 < HH) vloop2<0, 67, 17, 50, 1, false>(p, hlo, s);
  else                           vloop2<0, 67, 17, 50, 1, true>(p, hlo, s);
  int w0 = 2 * c2, w1 = w0 + 1;
  int wc0 = min(max(w0, 0), 511), wc1 = min(max(w1, 0), 511);
  int jlo0 = max(25 - wc0, 0), jhi0 = min(536 - wc0, 50);
  int jlo1 = max(25 - wc1, 0), jhi1 = min(536 - wc1, 50);
  float Tw0 = g_WCP[jhi0 + 1] - g_WCP[jlo0];
  float Tw1 = g_WCP[jhi1 + 1] - g_WCP[jlo1];
  const float2* sc = (const float2*)(score + (size_t)b * HWV);
#pragma unroll
  for (int k = 0; k < 17; k++) {
    int g = rowbase + k;
    bool rowok = (g >= 0 && g < HH);
    float2 e = make_float2(0.f, 0.f);
    if (rowok) e = sc[(size_t)(rowok ? g : 0) * 256 + c2c];
    int gc = min(max(g, 0), 511);
    int ilo = max(25 - gc, 0), ihi = min(536 - gc, 50);
    float Tv = g_WCP[ihi + 1] - g_WCP[ilo];
    float ld0 = 1e4f * (invz * s[k].x + 1e-6f * Tw0 * Tv);
    float ld1 = 1e4f * (invz * s[k].y + 1e-6f * Tw1 * Tv);
    float v0 = __expf(e.x) * invz * rsqrtf(ld0 + 1e-8f);
    float v1 = __expf(e.y) * invz * rsqrtf(ld1 + 1e-8f);
    bool ok = rowok && colok;
    s[k].x = ok ? v0 : -INFINITY;
    s[k].y = ok ? v1 : -INFINITY;
  }
  xch[ty][0][tx] = s[0];  xch[ty][1][tx] = s[1];
  xch[ty][2][tx] = s[15]; xch[ty][3][tx] = s[16];
  __syncthreads();
  float2 ninf = make_float2(-INFINITY, -INFINITY);
  float2 bm2 = (ty > 0) ? xch[ty - 1][2][tx] : ninf;
  float2 bm1 = (ty > 0) ? xch[ty - 1][3][tx] : ninf;
  float2 ap0 = (ty < 7) ? xch[ty + 1][0][tx] : ninf;
  float2 ap1 = (ty < 7) ? xch[ty + 1][1][tx] : ninf;
  float mv[6]; int mi[6]; int mine = 0;
#pragma unroll
  for (int k = 0; k < 17; k++) {
    float2 a  = (k >= 2) ? s[k - 2] : (k == 1 ? bm1 : bm2);
    float2 bb = (k >= 1) ? s[k - 1] : bm1;
    float2 c  = s[k];
    float2 d  = (k < 16) ? s[k + 1] : ap0;
    float2 ee = (k < 15) ? s[k + 2] : (k == 15 ? ap0 : ap1);
    float2 vm;
    vm.x = fmaxf(fmaxf(fmaxf(a.x, bb.x), fmaxf(c.x, d.x)), ee.x);
    vm.y = fmaxf(fmaxf(fmaxf(a.y, bb.y), fmaxf(c.y, d.y)), ee.y);
    float Lx = __shfl_up_sync(0xffffffffu, vm.x, 1);
    float Ly = __shfl_up_sync(0xffffffffu, vm.y, 1);
    float Rx = __shfl_down_sync(0xffffffffu, vm.x, 1);
    float Ry = __shfl_down_sync(0xffffffffu, vm.y, 1);
    float Mx = fmaxf(fmaxf(Lx, Ly), fmaxf(fmaxf(vm.x, vm.y), Rx));
    float My = fmaxf(fmaxf(Ly, vm.x), fmaxf(fmaxf(vm.y, Rx), Ry));
    int g = rowbase + k;
    bool rowT = (g >= r0) && (g < r0 + 128) && (g < HH);
    if (rowT && tx >= 1 && tx <= 30) {
      if (w0 < WW && c.x == Mx) {
        if (mine < 6) { mv[mine] = c.x; mi[mine] = g * WW + w0; }
        mine++;
      }
      if (w1 < WW && c.y == My) {
        if (mine < 6) { mv[mine] = c.y; mi[mine] = g * WW + w1; }
        mine++;
      }
    }
  }
  int cnt = min(mine, 6);
  int loc = 0;
  if (cnt) loc = atomicAdd(&scnt, cnt);
  __syncthreads();
  if (tid == 0) sbase = atomicAdd(&g_svcnt[b], scnt);
  __syncthreads();
  int base = sbase + loc;
  for (int i = 0; i < cnt; i++) {
    int pp = base + i;
    if (pp < SCAP) {
      g_svval[(size_t)b * SCAP + pp] = mv[i];
      g_svidx[(size_t)b * SCAP + pp] = mi[i];
    }
  }
}

// ---------------- top-2048 radix select + gather + masked LSE ----------------
__global__ __launch_bounds__(1024) void k_topk(const float* __restrict__ scoremap,
                                               const float* __restrict__ vA,
                                               const float* __restrict__ vB) {
  int x = blockIdx.x;
  int n = g_svcnt[x]; if (n > SCAP) n = SCAP;
  const float* vals = g_svval + (size_t)x * SCAP;
  const int* idxs = g_svidx + (size_t)x * SCAP;
  int* out = g_kidx + (size_t)x * MM;
  __shared__ int hist[256];
  __shared__ int suf[256];
  __shared__ float red[1024];
  __shared__ int sh_k, sh_dig, sh_ngt, sh_neq;
  int t = threadIdx.x;
  unsigned int prefix = 0;
  int k = MM;
  for (int lvl = 0; lvl < 4; lvl++) {
    int shift = 24 - 8 * lvl;
    if (t < 256) hist[t] = 0;
    __syncthreads();
    for (int i = t; i < n; i += 1024) {
      unsigned int u = __float_as_uint(vals[i]);
      bool ok = (lvl == 0) || ((u >> (shift + 8)) == (prefix >> (shift + 8)));
      if (ok) atomicAdd(&hist[(u >> shift) & 255], 1);
    }
    __syncthreads();
    if (t < 256) suf[t] = hist[t];
    __syncthreads();
    for (int off = 1; off < 256; off <<= 1) {
      int v = 0;
      if (t < 256) v = suf[t] + ((t + off < 256) ? suf[t + off] : 0);
      __syncthreads();
      if (t < 256) suf[t] = v;
      __syncthreads();
    }
    if (t < 256) {
      int nxt = (t == 255) ? 0 : suf[t + 1];
      if (suf[t] >= k && nxt < k) { sh_dig = t; sh_k = k - nxt; }
    }
    if (t == 0 && suf[0] < k) { sh_dig = 0; sh_k = k; }
    __syncthreads();
    k = sh_k;
    prefix |= ((unsigned int)sh_dig) << shift;
    __syncthreads();
  }
  unsigned int T = prefix;
  if (t == 0) { sh_ngt = 0; sh_neq = 0; }
  __syncthreads();
  for (int i = t; i < n; i += 1024) {
    unsigned int u = __float_as_uint(vals[i]);
    if (u > T) { int p = atomicAdd(&sh_ngt, 1); if (p < MM) out[p] = idxs[i]; }
  }
  __syncthreads();
  int base = sh_ngt;
  for (int i = t; i < n; i += 1024) {
    unsigned int u = __float_as_uint(vals[i]);
    if (u == T) { int p = atomicAdd(&sh_neq, 1); if (base + p < MM) out[base + p] = idxs[i]; }
  }
  __syncthreads();
  int dir = (x >= NB0) ? 1 : 0;
  int b = dir ? x - NB0 : x;
  const float* valid = (dir ? vB : vA) + (size_t)b * HWV;
  const float* logit = scoremap + (size_t)x * HWV;
  float mv = -INFINITY;
  for (int i = t; i < MM; i += 1024) {
    int id = out[i];
    float sl = logit[id];
    unsigned char lg = (valid[id] > 0.f) ? 1 : 0;
    g_ssl[(size_t)x * MM + i] = sl;
    g_slg[(size_t)x * MM + i] = lg;
    mv = fmaxf(mv, lg ? sl : -1e9f);
  }
  mv = blkMax1024(mv, red);
  float z = 0.f;
  for (int i = t; i < MM; i += 1024) {
    float ml = g_slg[(size_t)x * MM + i] ? g_ssl[(size_t)x * MM + i] : -1e9f;
    z += expf(ml - mv);
  }
  z = blkSum1024(z, red);
  if (t == 0) g_lse[x] = mv + logf(z);
}

// ---------------- distance + reward + weighted loss partials (256 thr, 1 query each) ----------------
__global__ __launch_bounds__(256) void k_dist(const float* __restrict__ wA,
                                              const float* __restrict__ wB) {
  __shared__ float4 sp[MM];
  __shared__ float red[256];
  int x = blockIdx.x, seg = blockIdx.y;   // seg 0..7
  int dir = (x >= NB0) ? 1 : 0;
  int b = dir ? x - NB0 : x;
  int oppx = dir ? b : (NB0 + b);
  const int* opp = g_kidx + (size_t)oppx * MM;
  const int* own = g_kidx + (size_t)x * MM;
  const float4* warp = (const float4*)((dir ? wB : wA) + (size_t)b * HWV * 4);
  int t = threadIdx.x;
  for (int i = t; i < MM; i += 256) {
    int id = opp[i]; int hh = id >> 9, ww = id & 511;
    float px = ((float)ww + 0.5f) * (2.0f / (float)WW) - 1.0f;
    float py = ((float)hh + 0.5f) * (2.0f / (float)HH) - 1.0f;
    sp[i] = make_float4(2.0f * px, 2.0f * py, fmaf(px, px, py * py), 0.f);
  }
  __syncthreads();
  int i0 = seg * 256 + t;
  float4 q0 = warp[own[i0]];
  float tx0 = q0.z, ty0 = q0.w;
  float a0 = -3.4e38f, a1 = -3.4e38f, a2 = -3.4e38f, a3 = -3.4e38f;
#pragma unroll 4
  for (int j = 0; j < MM; j += 4) {
    float4 p0 = sp[j], p1 = sp[j + 1], p2 = sp[j + 2], p3 = sp[j + 3];
    a0 = fmaxf(a0, fmaf(p0.x, tx0, fmaf(p0.y, ty0, -p0.z)));
    a1 = fmaxf(a1, fmaf(p1.x, tx0, fmaf(p1.y, ty0, -p1.z)));
    a2 = fmaxf(a2, fmaf(p2.x, tx0, fmaf(p2.y, ty0, -p2.z)));
    a3 = fmaxf(a3, fmaf(p3.x, tx0, fmaf(p3.y, ty0, -p3.z)));
  }
  float m0 = fmaxf(fmaxf(a0, a1), fmaxf(a2, a3));
  float dm0 = fmaxf(fmaf(tx0, tx0, ty0 * ty0) - m0, 0.f);
  float r0 = expf(-100.0f * sqrtf(dm0 + 1e-12f));
  float lse = g_lse[x];
  float c0 = g_slg[(size_t)x * MM + i0] ? r0 * (g_ssl[(size_t)x * MM + i0] - lse) : 0.f;
  float contrib = blkSum256(c0, red, t);
  if (t == 0) g_spart[x * 8 + seg] = contrib;
}

// ---------------- final combine ----------------
__global__ __launch_bounds__(256) void k_final(float* __restrict__ out) {
  __shared__ float sZ[128], sS[128], sV[128], sD[128];
  __shared__ float sm[16];
  __shared__ float ssp[128];
  int t = threadIdx.x;
  if (t < 128) {
    int img = t >> 3, seg = t & 7;
    float z = 0.f, s = 0.f, v = 0.f, d = 0.f;
    for (int j = 0; j < 16; j++) {
      const float* p = g_mpart + ((size_t)img * 128 + seg * 16 + j) * 4;
      z += p[0]; s += p[1]; v += p[2]; d += p[3];
    }
    sZ[t] = z; sS[t] = s; sV[t] = v; sD[t] = d;
    ssp[t] = g_spart[t];
  }
  __syncthreads();
  if (t < 16) {
    float z = 0.f, s = 0.f, v = 0.f, d = 0.f;
    for (int seg = 0; seg < 8; seg++) {
      z += sZ[t * 8 + seg]; s += sS[t * 8 + seg];
      v += sV[t * 8 + seg]; d += sD[t * 8 + seg];
    }
    float inv = 1.0f / s;
    sm[t] = inv * (d - v) - logf(s) + logf(z);
  }
  __syncthreads();
  if (t == 0) {
    float sp = 0.f;
    for (int i = 0; i < 128; i++) sp += ssp[i];
    float m = 0.f;
    for (int i = 0; i < 16; i++) m += sm[i];
    out[0] = -sp + m * (1.0f / 16.0f);
  }
}

// ---------------- host launcher ----------------
extern "C" void kernel_launch(void* const* d_in, const int* in_sizes, int n_in,
                              void* d_out, int out_size) {
  (void)in_sizes; (void)n_in; (void)out_size;
  const float* scoremap = (const float*)d_in[0];
  const float* wA = (const float*)d_in[1];
  const float* wB = (const float*)d_in[2];
  const float* vA = (const float*)d_in[3];
  const float* vB = (const float*)d_in[4];
  const float* hd = (const float*)d_in[5];
  float* out = (float*)d_out;

  dim3 hg(HH / 4, NB);
  dim3 hb(64, 4);
  dim3 vg(WW / 64, HH / 64, NB);
  dim3 vb(32, 8);
  dim3 cg(9, 4, NB);
  dim3 dg(NB, 8);

  k_hall<<<hg, hb>>>(scoremap, hd);
  k_vmatch<<<vg, vb>>>();
  k_vcnms<<<cg, vb>>>(scoremap);
  k_topk<<<NB, 1024>>>(scoremap, vA, vB);
  k_dist<<<dg, 256>>>(wA, wB);
  k_final<<<1, 256>>>(out);
}

// round 13
// speedup vs baseline: 1.9104x; 1.0440x over previous
#include <cuda_runtime.h>
#include <stdint.h>
#include <math.h>

#define HH 512
#define WW 512
#define HWV (HH*WW)
#define NB 16
#define NB0 8
#define MM 2048
#define SCAP 32768

// ---------------- compile-time taps ----------------
__host__ __device__ constexpr double cexp(double x) {
  double y = x < 0 ? -x : x;
  int n = (int)y;
  double f = y - n;
  double term = 1.0, sum = 1.0;
  for (int i = 1; i < 28; i++) { term = term * f / (double)i; sum += term; }
  double en = 1.0;
  for (int i = 0; i < n; i++) en *= 2.71828182845904523536028747135;
  double r = en * sum;
  return x < 0 ? 1.0 / r : r;
}
__host__ __device__ constexpr float gtap(int i) {
  double s = 0.0, gi = 0.0;
  for (int j = 0; j < 25; j++) {
    double xx = -1.0 + 2.0 * (double)j / 24.0;
    double g = cexp(-xx * xx / 0.5);
    if (j == i) gi = g;
    s += g;
  }
  return (float)(gi / s);
}
__host__ __device__ constexpr float wctap(int i) {
  double xx = -2.0 + 4.0 * (double)i / 50.0;
  return (float)cexp(-xx * xx);
}

// scalar scatter (horizontal conv)
template<int K, int KMAX, int Q, int D, int TMAX, int TSEL>
__device__ __forceinline__ void scat(float x, float* acc) {
  if constexpr (K < KMAX) {
    constexpr int t = Q - D - K;
    if constexpr (t >= 0 && t <= TMAX) {
      constexpr float tp = (TSEL == 0) ? gtap((t >= 0 && t <= TMAX) ? t : 0)
                                       : wctap((t >= 0 && t <= TMAX) ? t : 0);
      acc[K] = fmaf(tp, x, acc[K]);
    }
    scat<K + 1, KMAX, Q, D, TMAX, TSEL>(x, acc);
  }
}
template<int G4, int GMAX, int KMAX, int D, int TMAX, int TSEL>
__device__ __forceinline__ void conv4(const float4* w4, float* acc) {
  if constexpr (G4 < GMAX) {
    float4 X = w4[G4];
    scat<0, KMAX, 4 * G4 + 0, D, TMAX, TSEL>(X.x, acc);
    scat<0, KMAX, 4 * G4 + 1, D, TMAX, TSEL>(X.y, acc);
    scat<0, KMAX, 4 * G4 + 2, D, TMAX, TSEL>(X.z, acc);
    scat<0, KMAX, 4 * G4 + 3, D, TMAX, TSEL>(X.w, acc);
    conv4<G4 + 1, GMAX, KMAX, D, TMAX, TSEL>(w4, acc);
  }
}
// float2 scatter (vertical convs)
template<int K, int KMAX, int Q, int TMAX, int TSEL>
__device__ __forceinline__ void scat2(float2 x, float2* acc) {
  if constexpr (K < KMAX) {
    constexpr int t = Q - K;
    if constexpr (t >= 0 && t <= TMAX) {
      constexpr float tp = (TSEL == 0) ? gtap((t >= 0 && t <= TMAX) ? t : 0)
                                       : wctap((t >= 0 && t <= TMAX) ? t : 0);
      acc[K].x = fmaf(tp, x.x, acc[K].x);
      acc[K].y = fmaf(tp, x.y, acc[K].y);
    }
    scat2<K + 1, KMAX, Q, TMAX, TSEL>(x, acc);
  }
}
template<int R, int RMAX, int KMAX, int TMAX, int TSEL, bool CHK>
__device__ __forceinline__ void vloop2(const float2* p, int hlo, float2* acc) {
  if constexpr (R < RMAX) {
    float2 x = make_float2(0.f, 0.f);
    if (!CHK || ((unsigned)(hlo + R) < (unsigned)HH)) x = p[R * (WW / 2)];
    scat2<0, KMAX, R, TMAX, TSEL>(x, acc);
    vloop2<R + 1, RMAX, KMAX, TMAX, TSEL, CHK>(p, hlo, acc);
  }
}
template<int R, int RMAX, bool CHK>
__device__ __forceinline__ void vmloop2(const float2* ps, const float2* pd, int hlo,
                                        float2* as, float2* ad) {
  if constexpr (R < RMAX) {
    float2 xs = make_float2(0.f, 0.f), xd = make_float2(0.f, 0.f);
    if (!CHK || ((unsigned)(hlo + R) < (unsigned)HH)) {
      xs = ps[R * (WW / 2)];
      xd = pd[R * (WW / 2)];
    }
    scat2<0, 8, R, 24, 0>(xs, as);
    scat2<0, 8, R, 24, 0>(xd, ad);
    vmloop2<R + 1, RMAX, CHK>(ps, pd, hlo, as, ad);
  }
}

// ---------------- device scratch ----------------
__device__ float g_WCP[52];
__device__ float g_t1a[NB*HWV];
__device__ float g_t1b[NB*HWV];
__device__ float g_t1c[NB*HWV];
__device__ float g_ps[NB*128];
__device__ float g_mpart[NB*128*4];
__device__ int   g_svcnt[NB];
__device__ float g_svval[NB*SCAP];
__device__ int   g_svidx[NB*SCAP];
__device__ int   g_kidx[NB*MM];
__device__ float g_spart3[NB*8*3];   // per (x,seg): sum r*sl, sum r, sum exp(sl)  (legit only)

// ---------------- reductions ----------------
__device__ __forceinline__ float blkSum256(float v, float* red, int t) {
  red[t] = v; __syncthreads();
  for (int s = 128; s > 0; s >>= 1) {
    if (t < s) red[t] += red[t + s];
    __syncthreads();
  }
  float r = red[0]; __syncthreads();
  return r;
}

// ---------------- fused horizontal pass (+ init duties) ----------------
__global__ __launch_bounds__(256) void k_hall(const float* __restrict__ score,
                                              const float* __restrict__ hd) {
  __shared__ float sE[4][568];
  __shared__ float sD[4][536];
  __shared__ float red[256];
  int b = blockIdx.y;
  int tx = threadIdx.x, ty = threadIdx.y;    // (64,4)
  int h = blockIdx.x * 4 + ty;
  int tid = ty * 64 + tx;
  if (blockIdx.x == 0 && tid == 0) {
    g_svcnt[b] = 0;
    if (b == 0) {
      float p = 0.f;
      for (int i = 0; i < 51; i++) {
        float x = -2.0f + (4.0f / 50.0f) * (float)i;
        g_WCP[i] = p;
        p += expf(-x * x);
      }
      g_WCP[51] = p;
    }
  }
  const float* srow = score + (size_t)b * HWV + (size_t)h * WW;
  const float* drow = hd + (size_t)b * HWV + (size_t)h * WW;
  float esum = 0.f;
  for (int c = tx; c < 568; c += 64) {
    int w = c - 28;
    float e = 0.f;
    if (w >= 0 && w < WW) e = __expf(srow[w]);
    sE[ty][c] = e;
    esum += e;
  }
  for (int c = tx; c < 536; c += 64) {
    int w = c - 12;
    sD[ty][c] = (w >= 0 && w < WW) ? drow[w] : 0.f;
  }
  __syncthreads();
  int wbase = 8 * tx;
  size_t obase = (size_t)b * HWV + (size_t)h * WW + wbase;
  {
    float acc[8];
#pragma unroll
    for (int k = 0; k < 8; k++) acc[k] = 0.f;
    conv4<0, 16, 8, 3, 50, 1>((const float4*)&sE[ty][wbase], acc);
    float4* o = (float4*)(g_t1c + obase);
    o[0] = make_float4(acc[0], acc[1], acc[2], acc[3]);
    o[1] = make_float4(acc[4], acc[5], acc[6], acc[7]);
  }
  {
    float acc[8];
#pragma unroll
    for (int k = 0; k < 8; k++) acc[k] = 0.f;
    conv4<4, 12, 8, 16, 24, 0>((const float4*)&sE[ty][wbase], acc);
#pragma unroll
    for (int k = 0; k < 8; k++) {
      int w = wbase + k;
      if (w < 12 || w >= WW - 12) acc[k] = 0.f;
    }
    float4* o = (float4*)(g_t1a + obase);
    o[0] = make_float4(acc[0], acc[1], acc[2], acc[3]);
    o[1] = make_float4(acc[4], acc[5], acc[6], acc[7]);
  }
  {
    float acc[8];
#pragma unroll
    for (int k = 0; k < 8; k++) acc[k] = 0.f;
    conv4<0, 8, 8, 0, 24, 0>((const float4*)&sD[ty][wbase], acc);
    float4* o = (float4*)(g_t1b + obase);
    o[0] = make_float4(acc[0], acc[1], acc[2], acc[3]);
    o[1] = make_float4(acc[4], acc[5], acc[6], acc[7]);
  }
  esum = blkSum256(esum, red, tid);
  if (tid == 0) g_ps[b * 128 + blockIdx.x] = esum;
}

// ---------------- fused vertical convs (s + sd) + matchability partials ----------------
__global__ __launch_bounds__(256) void k_vmatch() {
  __shared__ float red[256];
  int b = blockIdx.z;
  int tx = threadIdx.x, ty = threadIdx.y;
  int c2 = blockIdx.x * 32 + tx;
  int hb = blockIdx.y * 64 + ty * 8;
  int tid = ty * 32 + tx;
  float pv = (tid < 128) ? g_ps[b * 128 + tid] : 0.f;
  float Z = blkSum256(pv, red, tid);
  float invz = 1.0f / Z;
  const float2* ps = (const float2*)(g_t1a + (size_t)b * HWV);
  const float2* pd = (const float2*)(g_t1b + (size_t)b * HWV);
  float2 as[8], ad[8];
#pragma unroll
  for (int k = 0; k < 8; k++) {
    as[k] = make_float2(0.f, 0.f);
    ad[k] = make_float2(0.f, 0.f);
  }
  int hlo = hb - 12;
  const float2* pps = ps + (size_t)hlo * (WW / 2) + c2;
  const float2* ppd = pd + (size_t)hlo * (WW / 2) + c2;
  if (hlo >= 0 && hlo + 31 < HH) vmloop2<0, 32, false>(pps, ppd, hlo, as, ad);
  else                           vmloop2<0, 32, true>(pps, ppd, hlo, as, ad);
  float zsum = 0.f, sdsum = 0.f, sdv = 0.f, sdlsd = 0.f;
#pragma unroll
  for (int k = 0; k < 8; k++) {
#pragma unroll
    for (int c = 0; c < 2; c++) {
      float a = c ? as[k].y : as[k].x;
      float sd = c ? ad[k].y : ad[k].x;
      float s = fmaf(invz, a, 1e-8f);
      zsum += s;
      sdsum += sd;
      if (sd > 0.f) {
        sdv = fmaf(sd, __logf(s), sdv);
        sdlsd = fmaf(sd, __logf(sd), sdlsd);
      }
    }
  }
  zsum = blkSum256(zsum, red, tid);
  sdsum = blkSum256(sdsum, red, tid);
  sdv = blkSum256(sdv, red, tid);
  sdlsd = blkSum256(sdlsd, red, tid);
  if (tid == 0) {
    int bi = blockIdx.y * 8 + blockIdx.x;
    float* p = g_mpart + ((size_t)b * 128 + bi) * 4;
    p[0] = zsum; p[1] = sdsum; p[2] = sdv; p[3] = sdlsd;
  }
}

// ---------------- fused: vertical coverage conv + reweight + 5x5 NMS ----------------
__global__ __launch_bounds__(256) void k_vcnms(const float* __restrict__ score) {
  __shared__ float red[256];
  __shared__ float2 xch[8][4][33];
  __shared__ int scnt, sbase;
  int b = blockIdx.z;
  int bx = blockIdx.x;
  int r0 = blockIdx.y * 128;
  int tx = threadIdx.x, ty = threadIdx.y;
  int tid = ty * 32 + tx;
  if (tid == 0) scnt = 0;
  float pv = (tid < 128) ? g_ps[b * 128 + tid] : 0.f;
  float Z = blkSum256(pv, red, tid);
  float invz = 1.0f / Z;
  int c2 = 30 * bx - 1 + tx;
  int c2c = min(max(c2, 0), 255);
  bool colok = (c2 >= 0 && c2 < 256);
  int rowbase = r0 - 2 + ty * 17;
  int hlo = rowbase - 25;
  const float2* pin = (const float2*)(g_t1c + (size_t)b * HWV);
  float2 s[17];
#pragma unroll
  for (int k = 0; k < 17; k++) s[k] = make_float2(0.f, 0.f);
  const float2* p = pin + (ptrdiff_t)hlo * 256 + c2c;
  if (hlo >= 0 && hlo + 66 < HH) vloop2<0, 67, 17, 50, 1, false>(p, hlo, s);
  else                           vloop2<0, 67, 17, 50, 1, true>(p, hlo, s);
  int w0 = 2 * c2, w1 = w0 + 1;
  int wc0 = min(max(w0, 0), 511), wc1 = min(max(w1, 0), 511);
  int jlo0 = max(25 - wc0, 0), jhi0 = min(536 - wc0, 50);
  int jlo1 = max(25 - wc1, 0), jhi1 = min(536 - wc1, 50);
  float Tw0 = g_WCP[jhi0 + 1] - g_WCP[jlo0];
  float Tw1 = g_WCP[jhi1 + 1] - g_WCP[jlo1];
  const float2* sc = (const float2*)(score + (size_t)b * HWV);
#pragma unroll
  for (int k = 0; k < 17; k++) {
    int g = rowbase + k;
    bool rowok = (g >= 0 && g < HH);
    float2 e = make_float2(0.f, 0.f);
    if (rowok) e = sc[(size_t)(rowok ? g : 0) * 256 + c2c];
    int gc = min(max(g, 0), 511);
    int ilo = max(25 - gc, 0), ihi = min(536 - gc, 50);
    float Tv = g_WCP[ihi + 1] - g_WCP[ilo];
    float ld0 = 1e4f * (invz * s[k].x + 1e-6f * Tw0 * Tv);
    float ld1 = 1e4f * (invz * s[k].y + 1e-6f * Tw1 * Tv);
    float v0 = __expf(e.x) * invz * rsqrtf(ld0 + 1e-8f);
    float v1 = __expf(e.y) * invz * rsqrtf(ld1 + 1e-8f);
    bool ok = rowok && colok;
    s[k].x = ok ? v0 : -INFINITY;
    s[k].y = ok ? v1 : -INFINITY;
  }
  xch[ty][0][tx] = s[0];  xch[ty][1][tx] = s[1];
  xch[ty][2][tx] = s[15]; xch[ty][3][tx] = s[16];
  __syncthreads();
  float2 ninf = make_float2(-INFINITY, -INFINITY);
  float2 bm2 = (ty > 0) ? xch[ty - 1][2][tx] : ninf;
  float2 bm1 = (ty > 0) ? xch[ty - 1][3][tx] : ninf;
  float2 ap0 = (ty < 7) ? xch[ty + 1][0][tx] : ninf;
  float2 ap1 = (ty < 7) ? xch[ty + 1][1][tx] : ninf;
  float mv[6]; int mi[6]; int mine = 0;
#pragma unroll
  for (int k = 0; k < 17; k++) {
    float2 a  = (k >= 2) ? s[k - 2] : (k == 1 ? bm1 : bm2);
    float2 bb = (k >= 1) ? s[k - 1] : bm1;
    float2 c  = s[k];
    float2 d  = (k < 16) ? s[k + 1] : ap0;
    float2 ee = (k < 15) ? s[k + 2] : (k == 15 ? ap0 : ap1);
    float2 vm;
    vm.x = fmaxf(fmaxf(fmaxf(a.x, bb.x), fmaxf(c.x, d.x)), ee.x);
    vm.y = fmaxf(fmaxf(fmaxf(a.y, bb.y), fmaxf(c.y, d.y)), ee.y);
    float Lx = __shfl_up_sync(0xffffffffu, vm.x, 1);
    float Ly = __shfl_up_sync(0xffffffffu, vm.y, 1);
    float Rx = __shfl_down_sync(0xffffffffu, vm.x, 1);
    float Ry = __shfl_down_sync(0xffffffffu, vm.y, 1);
    float Mx = fmaxf(fmaxf(Lx, Ly), fmaxf(fmaxf(vm.x, vm.y), Rx));
    float My = fmaxf(fmaxf(Ly, vm.x), fmaxf(fmaxf(vm.y, Rx), Ry));
    int g = rowbase + k;
    bool rowT = (g >= r0) && (g < r0 + 128) && (g < HH);
    if (rowT && tx >= 1 && tx <= 30) {
      if (w0 < WW && c.x == Mx) {
        if (mine < 6) { mv[mine] = c.x; mi[mine] = g * WW + w0; }
        mine++;
      }
      if (w1 < WW && c.y == My) {
        if (mine < 6) { mv[mine] = c.y; mi[mine] = g * WW + w1; }
        mine++;
      }
    }
  }
  int cnt = min(mine, 6);
  int loc = 0;
  if (cnt) loc = atomicAdd(&scnt, cnt);
  __syncthreads();
  if (tid == 0) sbase = atomicAdd(&g_svcnt[b], scnt);
  __syncthreads();
  int base = sbase + loc;
  for (int i = 0; i < cnt; i++) {
    int pp = base + i;
    if (pp < SCAP) {
      g_svval[(size_t)b * SCAP + pp] = mv[i];
      g_svidx[(size_t)b * SCAP + pp] = mi[i];
    }
  }
}

// ---------------- top-2048 radix select (warp-shuffle digit scan) ----------------
__global__ __launch_bounds__(1024) void k_topk() {
  int x = blockIdx.x;
  int n = g_svcnt[x]; if (n > SCAP) n = SCAP;
  const float* vals = g_svval + (size_t)x * SCAP;
  const int* idxs = g_svidx + (size_t)x * SCAP;
  int* out = g_kidx + (size_t)x * MM;
  __shared__ int hist[256];
  __shared__ int sh_k, sh_dig, sh_ngt, sh_neq;
  int t = threadIdx.x;
  unsigned int prefix = 0;
  int k = MM;
  for (int lvl = 0; lvl < 4; lvl++) {
    int shift = 24 - 8 * lvl;
    if (t < 256) hist[t] = 0;
    __syncthreads();
    for (int i = t; i < n; i += 1024) {
      unsigned int u = __float_as_uint(vals[i]);
      bool ok = (lvl == 0) || ((u >> (shift + 8)) == (prefix >> (shift + 8)));
      if (ok) atomicAdd(&hist[(u >> shift) & 255], 1);
    }
    __syncthreads();
    // single-warp suffix scan over 256 digits
    if (t < 32) {
      int base = t * 8;
      int h[8];
#pragma unroll
      for (int j = 0; j < 8; j++) h[j] = hist[base + j];
      int lsuf[8]; int run = 0;
#pragma unroll
      for (int j = 7; j >= 0; j--) { run += h[j]; lsuf[j] = run; }
      int tot = run;
      int s = tot;
#pragma unroll
      for (int off = 1; off < 32; off <<= 1) {
        int v = __shfl_down_sync(0xffffffffu, s, off);
        if (t + off < 32) s += v;
      }
      int excl = s - tot;   // sum over lanes > t
#pragma unroll
      for (int j = 0; j < 8; j++) {
        int sufj = excl + lsuf[j];
        int sufn = (j == 7) ? excl : excl + lsuf[j + 1];
        if (sufj >= k && sufn < k) { sh_dig = base + j; sh_k = k - sufn; }
      }
      if (t == 0 && s < k) { sh_dig = 0; sh_k = k; }
    }
    __syncthreads();
    k = sh_k;
    prefix |= ((unsigned int)sh_dig) << shift;
    __syncthreads();
  }
  unsigned int T = prefix;
  if (t == 0) { sh_ngt = 0; sh_neq = 0; }
  __syncthreads();
  for (int i = t; i < n; i += 1024) {
    unsigned int u = __float_as_uint(vals[i]);
    if (u > T) { int p = atomicAdd(&sh_ngt, 1); if (p < MM) out[p] = idxs[i]; }
  }
  __syncthreads();
  int base = sh_ngt;
  for (int i = t; i < n; i += 1024) {
    unsigned int u = __float_as_uint(vals[i]);
    if (u == T) { int p = atomicAdd(&sh_neq, 1); if (base + p < MM) out[base + p] = idxs[i]; }
  }
}

// ---------------- distance + reward + gather + sparse partials ----------------
__global__ __launch_bounds__(256) void k_dist(const float* __restrict__ scoremap,
                                              const float* __restrict__ wA,
                                              const float* __restrict__ wB,
                                              const float* __restrict__ vA,
                                              const float* __restrict__ vB) {
  __shared__ float4 sp[MM];
  __shared__ float red[256];
  int x = blockIdx.x, seg = blockIdx.y;   // seg 0..7
  int dir = (x >= NB0) ? 1 : 0;
  int b = dir ? x - NB0 : x;
  int oppx = dir ? b : (NB0 + b);
  const int* opp = g_kidx + (size_t)oppx * MM;
  const int* own = g_kidx + (size_t)x * MM;
  const float4* warp = (const float4*)((dir ? wB : wA) + (size_t)b * HWV * 4);
  const float* valid = (dir ? vB : vA) + (size_t)b * HWV;
  const float* logit = scoremap + (size_t)x * HWV;
  int t = threadIdx.x;
  for (int i = t; i < MM; i += 256) {
    int id = opp[i]; int hh = id >> 9, ww = id & 511;
    float px = ((float)ww + 0.5f) * (2.0f / (float)WW) - 1.0f;
    float py = ((float)hh + 0.5f) * (2.0f / (float)HH) - 1.0f;
    sp[i] = make_float4(2.0f * px, 2.0f * py, fmaf(px, px, py * py), 0.f);
  }
  __syncthreads();
  int i0 = seg * 256 + t;
  int id0 = own[i0];
  float4 q0 = warp[id0];
  float sl = logit[id0];
  bool lg = (valid[id0] > 0.f);
  float tx0 = q0.z, ty0 = q0.w;
  float a0 = -3.4e38f, a1 = -3.4e38f, a2 = -3.4e38f, a3 = -3.4e38f;
#pragma unroll 4
  for (int j = 0; j < MM; j += 4) {
    float4 p0 = sp[j], p1 = sp[j + 1], p2 = sp[j + 2], p3 = sp[j + 3];
    a0 = fmaxf(a0, fmaf(p0.x, tx0, fmaf(p0.y, ty0, -p0.z)));
    a1 = fmaxf(a1, fmaf(p1.x, tx0, fmaf(p1.y, ty0, -p1.z)));
    a2 = fmaxf(a2, fmaf(p2.x, tx0, fmaf(p2.y, ty0, -p2.z)));
    a3 = fmaxf(a3, fmaf(p3.x, tx0, fmaf(p3.y, ty0, -p3.z)));
  }
  float m0 = fmaxf(fmaxf(a0, a1), fmaxf(a2, a3));
  float dm0 = fmaxf(fmaf(tx0, tx0, ty0 * ty0) - m0, 0.f);
  float r = expf(-100.0f * sqrtf(dm0 + 1e-12f));
  float crsl = lg ? r * sl : 0.f;
  float cr   = lg ? r : 0.f;
  float cex  = lg ? expf(sl) : 0.f;
  crsl = blkSum256(crsl, red, t);
  cr = blkSum256(cr, red, t);
  cex = blkSum256(cex, red, t);
  if (t == 0) {
    float* p = g_spart3 + (size_t)(x * 8 + seg) * 3;
    p[0] = crsl; p[1] = cr; p[2] = cex;
  }
}

// ---------------- final combine ----------------
__global__ __launch_bounds__(256) void k_final(float* __restrict__ out) {
  __shared__ float sZ[128], sS[128], sV[128], sD[128];
  __shared__ float sm[16];
  __shared__ float ssx[16];
  int t = threadIdx.x;
  if (t < 128) {
    int img = t >> 3, seg = t & 7;
    float z = 0.f, s = 0.f, v = 0.f, d = 0.f;
    for (int j = 0; j < 16; j++) {
      const float* p = g_mpart + ((size_t)img * 128 + seg * 16 + j) * 4;
      z += p[0]; s += p[1]; v += p[2]; d += p[3];
    }
    sZ[t] = z; sS[t] = s; sV[t] = v; sD[t] = d;
  }
  __syncthreads();
  if (t < 16) {
    float z = 0.f, s = 0.f, v = 0.f, d = 0.f;
    for (int seg = 0; seg < 8; seg++) {
      z += sZ[t * 8 + seg]; s += sS[t * 8 + seg];
      v += sV[t * 8 + seg]; d += sD[t * 8 + seg];
    }
    float inv = 1.0f / s;
    sm[t] = inv * (d - v) - logf(s) + logf(z);
    // sparse per x
    float rsl = 0.f, rr = 0.f, ex = 0.f;
    for (int seg = 0; seg < 8; seg++) {
      const float* p = g_spart3 + (size_t)(t * 8 + seg) * 3;
      rsl += p[0]; rr += p[1]; ex += p[2];
    }
    ssx[t] = (rr > 0.f) ? (rsl - logf(ex) * rr) : 0.f;
  }
  __syncthreads();
  if (t == 0) {
    float sp = 0.f;
    for (int i = 0; i < 16; i++) sp += ssx[i];
    float m = 0.f;
    for (int i = 0; i < 16; i++) m += sm[i];
    out[0] = -sp + m * (1.0f / 16.0f);
  }
}

// ---------------- host launcher ----------------
extern "C" void kernel_launch(void* const* d_in, const int* in_sizes, int n_in,
                              void* d_out, int out_size) {
  (void)in_sizes; (void)n_in; (void)out_size;
  const float* scoremap = (const float*)d_in[0];
  const float* wA = (const float*)d_in[1];
  const float* wB = (const float*)d_in[2];
  const float* vA = (const float*)d_in[3];
  const float* vB = (const float*)d_in[4];
  const float* hd = (const float*)d_in[5];
  float* out = (float*)d_out;

  dim3 hg(HH / 4, NB);
  dim3 hb(64, 4);
  dim3 vg(WW / 64, HH / 64, NB);
  dim3 vb(32, 8);
  dim3 cg(9, 4, NB);
  dim3 dg(NB, 8);

  k_hall<<<hg, hb>>>(scoremap, hd);
  k_vmatch<<<vg, vb>>>();
  k_vcnms<<<cg, vb>>>(scoremap);
  k_topk<<<NB, 1024>>>();
  k_dist<<<dg, 256>>>(scoremap, wA, wB, vA, vB);
  k_final<<<1, 256>>>(out);
}